// round 11
// baseline (speedup 1.0000x reference)
#include <cuda_runtime.h>
#include <math.h>

// ---------------------------------------------------------------------------
// FusionHead: B=65536, D=192, H=3, HD=64, FP=128
// fp32 fused kernel, FFMA2 GEMMs. Round 9: M=48 token rows/block, RT=6,
// FFN split into two 192-hidden passes -> smem 110.6KB -> 2 blocks/SM
// (16 warps) with the improved L1-traffic ratio (L1 == fma == balanced).
// ---------------------------------------------------------------------------

#define D_MODEL 192
#define ROWS_PER_BLOCK 24          // batch rows per block
#define TOK_ROWS (2 * ROWS_PER_BLOCK)   // 48
#define NTHREADS 256

// scratch offsets (floats)
#define OFF_WPT    0
#define OFF_WTT    36864
#define OFF_INWGT  73728          // [3][192][192] gathered+transposed in-proj
#define OFF_INBG   184320         // [3][192] gathered in-proj bias
#define OFF_OUTWT  184896
#define OFF_FFN1T  221760         // [192][384]
#define OFF_FFN2T  295488         // [384][192]
#define OFF_CLS1T  369216
#define OFF_FPT    406080         // [192][128]
#define SCRATCH_FLOATS 430656

__device__ float g_scratch[SCRATCH_FLOATS];

// ---------------------------------------------------------------------------
// Merged prep kernel (transposes + in-proj gather), grid-stride.
// ---------------------------------------------------------------------------
__global__ void k_prep(const float* __restrict__ Wp, const float* __restrict__ Wt,
                       const float* __restrict__ out_w,
                       const float* __restrict__ ffn_w1, const float* __restrict__ ffn_w2,
                       const float* __restrict__ cls_w1, const float* __restrict__ fp_w,
                       const float* __restrict__ in_w,  const float* __restrict__ in_b) {
    const int t0 = blockIdx.x * blockDim.x + threadIdx.x;
    const int stride = gridDim.x * blockDim.x;
    auto tr = [&](const float* src, int N, int K, int off) {
        for (int i = t0; i < N * K; i += stride) {
            int n = i / K, k = i % K;
            g_scratch[off + k * N + n] = src[i];
        }
    };
    tr(Wp,     192, 192, OFF_WPT);
    tr(Wt,     192, 192, OFF_WTT);
    tr(out_w,  192, 192, OFF_OUTWT);
    tr(ffn_w1, 384, 192, OFF_FFN1T);
    tr(ffn_w2, 192, 384, OFF_FFN2T);
    tr(cls_w1, 192, 192, OFF_CLS1T);
    tr(fp_w,   128, 192, OFF_FPT);
    for (int idx = t0; idx < 3 * 192 * 192; idx += stride) {
        int h   = idx / (192 * 192);
        int rem = idx % (192 * 192);
        int k   = rem / 192;
        int j   = rem % 192;
        int part = j / 64, jj = j % 64;
        int srcrow = part * 192 + h * 64 + jj;
        g_scratch[OFF_INWGT + idx] = in_w[srcrow * 192 + k];
        if (k == 0) g_scratch[OFF_INBG + h * 192 + j] = in_b[srcrow];
    }
}

// ---------------------------------------------------------------------------
// f32x2 helpers
// ---------------------------------------------------------------------------
__device__ __forceinline__ unsigned long long pack2(float lo, float hi) {
    unsigned long long r;
    asm("mov.b64 %0, {%1, %2};" : "=l"(r) : "f"(lo), "f"(hi));
    return r;
}
__device__ __forceinline__ void unpack2(unsigned long long p, float& lo, float& hi) {
    asm("mov.b64 {%0, %1}, %2;" : "=f"(lo), "=f"(hi) : "l"(p));
}
__device__ __forceinline__ unsigned long long ffma2(
    unsigned long long a, unsigned long long b, unsigned long long c) {
    unsigned long long d;
    asm("fma.rn.f32x2 %0, %1, %2, %3;" : "=l"(d) : "l"(a), "l"(b), "l"(c));
    return d;
}

__device__ __forceinline__ float wredsum(float v) {
    #pragma unroll
    for (int o = 16; o > 0; o >>= 1) v += __shfl_xor_sync(0xffffffffu, v, o);
    return v;
}

// ---------------------------------------------------------------------------
// GEMM, f32x2 accumulators over column pairs, double-buffered weight loads.
// out[r][n] = act[r][:] . WT[:][n] (+ bias | + existing out).
// 8 warps: warp = row group (RT = M/8), lanes -> column pairs. K % 4 == 0.
// ADDTO: skip bias, add previously stored out values (FFN pass 2).
// ---------------------------------------------------------------------------
template<int M, int N, int K, bool RELU, bool ADDTO>
__device__ __forceinline__ void gemm2(
    const float* __restrict__ act, int actStride,
    const float* __restrict__ WT, int wN,
    const float* __restrict__ bias,
    float* __restrict__ out, int outStride, int tid)
{
    static_assert(K % 4 == 0, "K must be divisible by 4");
    const int tx = tid & 31;
    const int ty = tid >> 5;
    constexpr int RT = M / 8;       // rows per thread
    constexpr int NP = N / 64;      // col pairs per thread
    unsigned long long acc[RT][NP];
    #pragma unroll
    for (int i = 0; i < RT; ++i)
        #pragma unroll
        for (int c = 0; c < NP; ++c) acc[i][c] = 0ull;

    const float* a0 = act + (ty * RT) * actStride;
    const float* wb = WT + 2 * tx;

    unsigned long long wA[2][NP], wB[2][NP];

#define GEMM_LOAD(WBUF, KN)                                                     \
    _Pragma("unroll")                                                           \
    for (int c = 0; c < NP; ++c) {                                              \
        WBUF[0][c] = *reinterpret_cast<const unsigned long long*>(              \
                         wb + (KN) * wN + 64 * c);                              \
        WBUF[1][c] = *reinterpret_cast<const unsigned long long*>(              \
                         wb + ((KN) + 1) * wN + 64 * c);                        \
    }

#define GEMM_STEP(WBUF, KOFF)                                                   \
    _Pragma("unroll")                                                           \
    for (int i = 0; i < RT; ++i) {                                              \
        float2 a = *reinterpret_cast<const float2*>(a0 + i * actStride + k + (KOFF)); \
        unsigned long long aa0 = pack2(a.x, a.x);                               \
        unsigned long long aa1 = pack2(a.y, a.y);                               \
        _Pragma("unroll")                                                       \
        for (int c = 0; c < NP; ++c) {                                          \
            acc[i][c] = ffma2(aa0, WBUF[0][c], acc[i][c]);                      \
            acc[i][c] = ffma2(aa1, WBUF[1][c], acc[i][c]);                      \
        }                                                                       \
    }

    GEMM_LOAD(wA, 0);
    GEMM_LOAD(wB, 2);

    #pragma unroll 1
    for (int k = 0; k < K; k += 4) {
        int k4 = (k + 4 < K) ? k + 4 : 0;   // clamped: tail loads are dead
        int k6 = (k + 6 < K) ? k + 6 : 0;
        GEMM_STEP(wA, 0); GEMM_LOAD(wA, k4);
        GEMM_STEP(wB, 2); GEMM_LOAD(wB, k6);
    }
#undef GEMM_LOAD
#undef GEMM_STEP

    #pragma unroll
    for (int i = 0; i < RT; ++i)
        #pragma unroll
        for (int c = 0; c < NP; ++c) {
            int col = 2 * (tx + 32 * c);
            float* op = out + (ty * RT + i) * outStride + col;
            float lo, hi;
            unpack2(acc[i][c], lo, hi);
            if (ADDTO) {
                float2 prev = *reinterpret_cast<const float2*>(op);
                lo += prev.x; hi += prev.y;
            } else {
                lo += bias[col]; hi += bias[col + 1];
            }
            if (RELU) { lo = fmaxf(lo, 0.0f); hi = fmaxf(hi, 0.0f); }
            *reinterpret_cast<float2*>(op) = make_float2(lo, hi);
        }
}

// LayerNorm over 192 dims of A[row] + Bb[row] -> Out (stride 192), 48 rows.
__device__ __forceinline__ void ln48(
    const float* __restrict__ A, int strideA,
    const float* __restrict__ Bb, int strideB,
    float* __restrict__ Out,
    const float* __restrict__ g, const float* __restrict__ be, int tid)
{
    int warp = tid >> 5, lane = tid & 31;
    #pragma unroll
    for (int rr = 0; rr < 6; ++rr) {
        int row = warp * 6 + rr;
        float v[6];
        float s = 0.0f;
        #pragma unroll
        for (int i = 0; i < 6; ++i) {
            int d = lane + 32 * i;
            v[i] = A[row * strideA + d] + Bb[row * strideB + d];
            s += v[i];
        }
        s = wredsum(s);
        float mean = s * (1.0f / 192.0f);
        float sq = 0.0f;
        #pragma unroll
        for (int i = 0; i < 6; ++i) { float dl = v[i] - mean; sq = fmaf(dl, dl, sq); }
        sq = wredsum(sq);
        float rstd = rsqrtf(sq * (1.0f / 192.0f) + 1e-5f);
        #pragma unroll
        for (int i = 0; i < 6; ++i) {
            int d = lane + 32 * i;
            Out[row * 192 + d] = (v[i] - mean) * rstd * g[d] + be[d];
        }
    }
}

// ---------------------------------------------------------------------------
// Main fused kernel: 24 batch rows (48 token rows), 256 threads, 2 blocks/SM.
// smem: s_seq [48][192] + s_buf [48][384] = 110592 B.
// ---------------------------------------------------------------------------
__global__ __launch_bounds__(NTHREADS, 2) void fusion_kernel(
    const float* __restrict__ perc, const float* __restrict__ tech,
    const float* __restrict__ bp,   const float* __restrict__ bt,
    const float* __restrict__ out_b,
    const float* __restrict__ ffn_b1, const float* __restrict__ ffn_b2,
    const float* __restrict__ ln1_g, const float* __restrict__ ln1_b,
    const float* __restrict__ ln2_g, const float* __restrict__ ln2_b,
    const float* __restrict__ cls_b1,
    const float* __restrict__ cls_w2, const float* __restrict__ cls_b2,
    const float* __restrict__ fp_b,
    float* __restrict__ out, int B)
{
    extern __shared__ float sm[];
    float* s_seq = sm;                        // [48][192]
    float* s_buf = sm + TOK_ROWS * 192;       // [48][384]: A = cols 0:192, Bzone = 192:384
    const float* gs = g_scratch;

    const int tid  = threadIdx.x;
    const int warp = tid >> 5, lane = tid & 31;
    const int b0   = blockIdx.x * ROWS_PER_BLOCK;

    // ---- load inputs: perc -> A, tech -> Bzone
    for (int idx = tid; idx < ROWS_PER_BLOCK * 48; idx += NTHREADS) {
        int r = idx / 48, q4 = idx % 48;
        int row = b0 + r; if (row >= B) row = B - 1;
        float4 pv = reinterpret_cast<const float4*>(perc + row * 192)[q4];
        float4 tv = reinterpret_cast<const float4*>(tech + row * 192)[q4];
        reinterpret_cast<float4*>(s_buf + r * 384)[q4] = pv;
        reinterpret_cast<float4*>(s_buf + r * 384 + 192)[q4] = tv;
    }
    __syncthreads();

    // ---- projections: p -> token rows 2r, t -> 2r+1 (s_seq, row stride 192)
    gemm2<24, 192, 192, false, false>(s_buf,       384, gs + OFF_WPT, 192, bp, s_seq,       384, tid);
    gemm2<24, 192, 192, false, false>(s_buf + 192, 384, gs + OFF_WTT, 192, bt, s_seq + 192, 384, tid);
    __syncthreads();

    // ---- per-head: qkv -> A; attention ctx -> Bzone cols h*64
    for (int h = 0; h < 3; ++h) {
        gemm2<48, 192, 192, false, false>(s_seq, 192, gs + OFF_INWGT + h * 36864, 192,
                                          gs + OFF_INBG + h * 192, s_buf, 384, tid);
        __syncthreads();
        #pragma unroll
        for (int pp = 0; pp < 3; ++pp) {
            int p = warp * 3 + pp;
            float* r0 = s_buf + (2 * p) * 384;
            float* r1 = r0 + 384;
            float q0a = r0[lane],       q0b = r0[lane + 32];
            float k0a = r0[64 + lane],  k0b = r0[96 + lane];
            float v0a = r0[128 + lane], v0b = r0[160 + lane];
            float q1a = r1[lane],       q1b = r1[lane + 32];
            float k1a = r1[64 + lane],  k1b = r1[96 + lane];
            float v1a = r1[128 + lane], v1b = r1[160 + lane];
            float s00 = wredsum(q0a * k0a + q0b * k0b) * 0.125f;
            float s01 = wredsum(q0a * k1a + q0b * k1b) * 0.125f;
            float s10 = wredsum(q1a * k0a + q1b * k0b) * 0.125f;
            float s11 = wredsum(q1a * k1a + q1b * k1b) * 0.125f;
            float m0 = fmaxf(s00, s01);
            float e00 = __expf(s00 - m0), e01 = __expf(s01 - m0);
            float i0 = 1.0f / (e00 + e01);
            float a00 = e00 * i0, a01 = e01 * i0;
            float m1 = fmaxf(s10, s11);
            float e10 = __expf(s10 - m1), e11 = __expf(s11 - m1);
            float i1 = 1.0f / (e10 + e11);
            float a10 = e10 * i1, a11 = e11 * i1;
            int cb = 192 + h * 64;
            r0[cb + lane]      = a00 * v0a + a01 * v1a;
            r0[cb + lane + 32] = a00 * v0b + a01 * v1b;
            r1[cb + lane]      = a10 * v0a + a11 * v1a;
            r1[cb + lane + 32] = a10 * v0b + a11 * v1b;
        }
        __syncthreads();
    }

    // ---- out-proj: ctx (Bzone) -> attn_out (A)
    gemm2<48, 192, 192, false, false>(s_buf + 192, 384, gs + OFF_OUTWT, 192, out_b, s_buf, 384, tid);
    __syncthreads();

    // ---- LN1: x1 = LN(seq + attn_out) -> s_seq
    ln48(s_seq, 192, s_buf, 384, s_seq, ln1_g, ln1_b, tid);
    __syncthreads();

    // ---- FFN, two passes of 192 hidden each
    // pass 1: hidden1 -> A ; partial out (with bias) -> Bzone
    gemm2<48, 192, 192, true,  false>(s_seq, 192, gs + OFF_FFN1T, 384, ffn_b1, s_buf, 384, tid);
    __syncthreads();
    gemm2<48, 192, 192, false, false>(s_buf, 384, gs + OFF_FFN2T, 192, ffn_b2, s_buf + 192, 384, tid);
    __syncthreads();
    // pass 2: hidden2 -> A ; accumulate into Bzone
    gemm2<48, 192, 192, true,  false>(s_seq, 192, gs + OFF_FFN1T + 192, 384, ffn_b1 + 192, s_buf, 384, tid);
    __syncthreads();
    gemm2<48, 192, 192, false, true >(s_buf, 384, gs + OFF_FFN2T + 192 * 192, 192, ffn_b2, s_buf + 192, 384, tid);
    __syncthreads();

    // ---- LN2: x2 = LN(x1 + ffn_out) -> s_seq
    ln48(s_seq, 192, s_buf + 192, 384, s_seq, ln2_g, ln2_b, tid);
    __syncthreads();

    // ---- pool: z[r] -> A rows 0:24
    for (int idx = tid; idx < ROWS_PER_BLOCK * 192; idx += NTHREADS) {
        int r = idx / 192, d = idx % 192;
        s_buf[r * 384 + d] = 0.5f * (s_seq[(2 * r) * 192 + d] + s_seq[(2 * r + 1) * 192 + d]);
    }
    __syncthreads();

    // ---- heads: cls1 (relu) -> Bzone rows 0:24 ; fp -> A rows 24:48
    gemm2<24, 192, 192, true,  false>(s_buf, 384, gs + OFF_CLS1T, 192, cls_b1, s_buf + 192, 384, tid);
    gemm2<24, 128, 192, false, false>(s_buf, 384, gs + OFF_FPT,   128, fp_b,   s_buf + ROWS_PER_BLOCK * 384, 384, tid);
    __syncthreads();

    // ---- cls2 + sigmoid: 24 rows x 3 logits
    if (tid < 72) {
        int r = tid / 3, j = tid % 3;
        const float4* c1 = reinterpret_cast<const float4*>(s_buf + r * 384 + 192);
        const float4* w2 = reinterpret_cast<const float4*>(cls_w2 + j * 192);
        float acc = 0.0f;
        #pragma unroll 8
        for (int q = 0; q < 48; ++q) {
            float4 a = c1[q], w = w2[q];
            acc = fmaf(a.x, w.x, acc); acc = fmaf(a.y, w.y, acc);
            acc = fmaf(a.z, w.z, acc); acc = fmaf(a.w, w.w, acc);
        }
        acc += cls_b2[j];
        float prob = 1.0f / (1.0f + __expf(-acc));
        int row = b0 + r;
        if (row < B) out[j * B + row] = prob;
    }

    // ---- fp normalize + store: warp handles rows 3w..3w+2
    #pragma unroll
    for (int rr = 0; rr < 3; ++rr) {
        int r = warp * 3 + rr;
        const float* fpv = s_buf + (ROWS_PER_BLOCK + r) * 384;
        float f[4];
        float ss = 0.0f;
        #pragma unroll
        for (int i = 0; i < 4; ++i) { f[i] = fpv[lane + 32 * i]; ss = fmaf(f[i], f[i], ss); }
        ss = wredsum(ss);
        float inv = 1.0f / fmaxf(sqrtf(ss), 1e-12f);
        int row = b0 + r;
        if (row < B) {
            float* o = out + 3 * B + row * 128;
            #pragma unroll
            for (int i = 0; i < 4; ++i) o[lane + 32 * i] = f[i] * inv;
        }
    }
}

// ---------------------------------------------------------------------------
// Launch
// ---------------------------------------------------------------------------
extern "C" void kernel_launch(void* const* d_in, const int* in_sizes, int n_in,
                              void* d_out, int out_size) {
    const float* perc   = (const float*)d_in[0];
    const float* tech   = (const float*)d_in[1];
    const float* Wp     = (const float*)d_in[2];
    const float* bp     = (const float*)d_in[3];
    const float* Wt     = (const float*)d_in[4];
    const float* bt     = (const float*)d_in[5];
    const float* in_w   = (const float*)d_in[6];
    const float* in_b   = (const float*)d_in[7];
    const float* out_w  = (const float*)d_in[8];
    const float* out_b  = (const float*)d_in[9];
    const float* ffn_w1 = (const float*)d_in[10];
    const float* ffn_b1 = (const float*)d_in[11];
    const float* ffn_w2 = (const float*)d_in[12];
    const float* ffn_b2 = (const float*)d_in[13];
    const float* ln1_g  = (const float*)d_in[14];
    const float* ln1_b  = (const float*)d_in[15];
    const float* ln2_g  = (const float*)d_in[16];
    const float* ln2_b  = (const float*)d_in[17];
    const float* cls_w1 = (const float*)d_in[18];
    const float* cls_b1 = (const float*)d_in[19];
    const float* cls_w2 = (const float*)d_in[20];
    const float* cls_b2 = (const float*)d_in[21];
    const float* fp_w   = (const float*)d_in[22];
    const float* fp_b   = (const float*)d_in[23];
    float* outp = (float*)d_out;

    const int B = in_sizes[0] / D_MODEL;

    // merged weight prep (runs inside the graph each replay)
    k_prep<<<296, 256>>>(Wp, Wt, out_w, ffn_w1, ffn_w2, cls_w1, fp_w, in_w, in_b);

    const int smemBytes = (TOK_ROWS * 192 + TOK_ROWS * 384) * (int)sizeof(float); // 110592
    cudaFuncSetAttribute(fusion_kernel, cudaFuncAttributeMaxDynamicSharedMemorySize, smemBytes);

    int grid = (B + ROWS_PER_BLOCK - 1) / ROWS_PER_BLOCK;
    fusion_kernel<<<grid, NTHREADS, smemBytes>>>(
        perc, tech, bp, bt, out_b, ffn_b1, ffn_b2,
        ln1_g, ln1_b, ln2_g, ln2_b, cls_b1, cls_w2, cls_b2, fp_b,
        outp, B);
}

// round 15
// speedup vs baseline: 1.5831x; 1.5831x over previous
#include <cuda_runtime.h>
#include <math.h>

// ---------------------------------------------------------------------------
// FusionHead: B=65536, D=192, H=3, HD=64, FP=128
// fp32 fused kernel, FFMA2 GEMMs. Round 9: M=48 token rows/block, RT=6,
// FFN split into two 192-hidden passes -> smem 110.6KB -> 2 blocks/SM
// (16 warps) with the improved L1-traffic ratio (L1 == fma == balanced).
// ---------------------------------------------------------------------------

#define D_MODEL 192
#define ROWS_PER_BLOCK 24          // batch rows per block
#define TOK_ROWS (2 * ROWS_PER_BLOCK)   // 48
#define NTHREADS 256

// scratch offsets (floats)
#define OFF_WPT    0
#define OFF_WTT    36864
#define OFF_INWGT  73728          // [3][192][192] gathered+transposed in-proj
#define OFF_INBG   184320         // [3][192] gathered in-proj bias
#define OFF_OUTWT  184896
#define OFF_FFN1T  221760         // [192][384]
#define OFF_FFN2T  295488         // [384][192]
#define OFF_CLS1T  369216
#define OFF_FPT    406080         // [192][128]
#define SCRATCH_FLOATS 430656

__device__ float g_scratch[SCRATCH_FLOATS];

// ---------------------------------------------------------------------------
// Merged prep kernel (transposes + in-proj gather), grid-stride.
// ---------------------------------------------------------------------------
__global__ void k_prep(const float* __restrict__ Wp, const float* __restrict__ Wt,
                       const float* __restrict__ out_w,
                       const float* __restrict__ ffn_w1, const float* __restrict__ ffn_w2,
                       const float* __restrict__ cls_w1, const float* __restrict__ fp_w,
                       const float* __restrict__ in_w,  const float* __restrict__ in_b) {
    const int t0 = blockIdx.x * blockDim.x + threadIdx.x;
    const int stride = gridDim.x * blockDim.x;
    auto tr = [&](const float* src, int N, int K, int off) {
        for (int i = t0; i < N * K; i += stride) {
            int n = i / K, k = i % K;
            g_scratch[off + k * N + n] = src[i];
        }
    };
    tr(Wp,     192, 192, OFF_WPT);
    tr(Wt,     192, 192, OFF_WTT);
    tr(out_w,  192, 192, OFF_OUTWT);
    tr(ffn_w1, 384, 192, OFF_FFN1T);
    tr(ffn_w2, 192, 384, OFF_FFN2T);
    tr(cls_w1, 192, 192, OFF_CLS1T);
    tr(fp_w,   128, 192, OFF_FPT);
    for (int idx = t0; idx < 3 * 192 * 192; idx += stride) {
        int h   = idx / (192 * 192);
        int rem = idx % (192 * 192);
        int k   = rem / 192;
        int j   = rem % 192;
        int part = j / 64, jj = j % 64;
        int srcrow = part * 192 + h * 64 + jj;
        g_scratch[OFF_INWGT + idx] = in_w[srcrow * 192 + k];
        if (k == 0) g_scratch[OFF_INBG + h * 192 + j] = in_b[srcrow];
    }
}

// ---------------------------------------------------------------------------
// f32x2 helpers
// ---------------------------------------------------------------------------
__device__ __forceinline__ unsigned long long pack2(float lo, float hi) {
    unsigned long long r;
    asm("mov.b64 %0, {%1, %2};" : "=l"(r) : "f"(lo), "f"(hi));
    return r;
}
__device__ __forceinline__ void unpack2(unsigned long long p, float& lo, float& hi) {
    asm("mov.b64 {%0, %1}, %2;" : "=f"(lo), "=f"(hi) : "l"(p));
}
__device__ __forceinline__ unsigned long long ffma2(
    unsigned long long a, unsigned long long b, unsigned long long c) {
    unsigned long long d;
    asm("fma.rn.f32x2 %0, %1, %2, %3;" : "=l"(d) : "l"(a), "l"(b), "l"(c));
    return d;
}

__device__ __forceinline__ float wredsum(float v) {
    #pragma unroll
    for (int o = 16; o > 0; o >>= 1) v += __shfl_xor_sync(0xffffffffu, v, o);
    return v;
}

// ---------------------------------------------------------------------------
// GEMM, f32x2 accumulators over column pairs, double-buffered weight loads.
// out[r][n] = act[r][:] . WT[:][n] (+ bias | + existing out).
// 8 warps: warp = row group (RT = M/8), lanes -> column pairs. K % 4 == 0.
// ADDTO: skip bias, add previously stored out values (FFN pass 2).
// ---------------------------------------------------------------------------
template<int M, int N, int K, bool RELU, bool ADDTO>
__device__ __forceinline__ void gemm2(
    const float* __restrict__ act, int actStride,
    const float* __restrict__ WT, int wN,
    const float* __restrict__ bias,
    float* __restrict__ out, int outStride, int tid)
{
    static_assert(K % 4 == 0, "K must be divisible by 4");
    const int tx = tid & 31;
    const int ty = tid >> 5;
    constexpr int RT = M / 8;       // rows per thread
    constexpr int NP = N / 64;      // col pairs per thread
    unsigned long long acc[RT][NP];
    #pragma unroll
    for (int i = 0; i < RT; ++i)
        #pragma unroll
        for (int c = 0; c < NP; ++c) acc[i][c] = 0ull;

    const float* a0 = act + (ty * RT) * actStride;
    const float* wb = WT + 2 * tx;

    unsigned long long wA[2][NP], wB[2][NP];

#define GEMM_LOAD(WBUF, KN)                                                     \
    _Pragma("unroll")                                                           \
    for (int c = 0; c < NP; ++c) {                                              \
        WBUF[0][c] = *reinterpret_cast<const unsigned long long*>(              \
                         wb + (KN) * wN + 64 * c);                              \
        WBUF[1][c] = *reinterpret_cast<const unsigned long long*>(              \
                         wb + ((KN) + 1) * wN + 64 * c);                        \
    }

#define GEMM_STEP(WBUF, KOFF)                                                   \
    _Pragma("unroll")                                                           \
    for (int i = 0; i < RT; ++i) {                                              \
        float2 a = *reinterpret_cast<const float2*>(a0 + i * actStride + k + (KOFF)); \
        unsigned long long aa0 = pack2(a.x, a.x);                               \
        unsigned long long aa1 = pack2(a.y, a.y);                               \
        _Pragma("unroll")                                                       \
        for (int c = 0; c < NP; ++c) {                                          \
            acc[i][c] = ffma2(aa0, WBUF[0][c], acc[i][c]);                      \
            acc[i][c] = ffma2(aa1, WBUF[1][c], acc[i][c]);                      \
        }                                                                       \
    }

    GEMM_LOAD(wA, 0);
    GEMM_LOAD(wB, 2);

    #pragma unroll 1
    for (int k = 0; k < K; k += 4) {
        int k4 = (k + 4 < K) ? k + 4 : 0;   // clamped: tail loads are dead
        int k6 = (k + 6 < K) ? k + 6 : 0;
        GEMM_STEP(wA, 0); GEMM_LOAD(wA, k4);
        GEMM_STEP(wB, 2); GEMM_LOAD(wB, k6);
    }
#undef GEMM_LOAD
#undef GEMM_STEP

    #pragma unroll
    for (int i = 0; i < RT; ++i)
        #pragma unroll
        for (int c = 0; c < NP; ++c) {
            int col = 2 * (tx + 32 * c);
            float* op = out + (ty * RT + i) * outStride + col;
            float lo, hi;
            unpack2(acc[i][c], lo, hi);
            if (ADDTO) {
                float2 prev = *reinterpret_cast<const float2*>(op);
                lo += prev.x; hi += prev.y;
            } else {
                lo += bias[col]; hi += bias[col + 1];
            }
            if (RELU) { lo = fmaxf(lo, 0.0f); hi = fmaxf(hi, 0.0f); }
            *reinterpret_cast<float2*>(op) = make_float2(lo, hi);
        }
}

// LayerNorm over 192 dims of A[row] + Bb[row] -> Out (stride 192), 48 rows.
__device__ __forceinline__ void ln48(
    const float* __restrict__ A, int strideA,
    const float* __restrict__ Bb, int strideB,
    float* __restrict__ Out,
    const float* __restrict__ g, const float* __restrict__ be, int tid)
{
    int warp = tid >> 5, lane = tid & 31;
    #pragma unroll
    for (int rr = 0; rr < 6; ++rr) {
        int row = warp * 6 + rr;
        float v[6];
        float s = 0.0f;
        #pragma unroll
        for (int i = 0; i < 6; ++i) {
            int d = lane + 32 * i;
            v[i] = A[row * strideA + d] + Bb[row * strideB + d];
            s += v[i];
        }
        s = wredsum(s);
        float mean = s * (1.0f / 192.0f);
        float sq = 0.0f;
        #pragma unroll
        for (int i = 0; i < 6; ++i) { float dl = v[i] - mean; sq = fmaf(dl, dl, sq); }
        sq = wredsum(sq);
        float rstd = rsqrtf(sq * (1.0f / 192.0f) + 1e-5f);
        #pragma unroll
        for (int i = 0; i < 6; ++i) {
            int d = lane + 32 * i;
            Out[row * 192 + d] = (v[i] - mean) * rstd * g[d] + be[d];
        }
    }
}

// ---------------------------------------------------------------------------
// Main fused kernel: 24 batch rows (48 token rows), 256 threads, 2 blocks/SM.
// smem: s_seq [48][192] + s_buf [48][384] = 110592 B.
// ---------------------------------------------------------------------------
__global__ __launch_bounds__(NTHREADS, 2) void fusion_kernel(
    const float* __restrict__ perc, const float* __restrict__ tech,
    const float* __restrict__ bp,   const float* __restrict__ bt,
    const float* __restrict__ out_b,
    const float* __restrict__ ffn_b1, const float* __restrict__ ffn_b2,
    const float* __restrict__ ln1_g, const float* __restrict__ ln1_b,
    const float* __restrict__ ln2_g, const float* __restrict__ ln2_b,
    const float* __restrict__ cls_b1,
    const float* __restrict__ cls_w2, const float* __restrict__ cls_b2,
    const float* __restrict__ fp_b,
    float* __restrict__ out, int B)
{
    extern __shared__ float sm[];
    float* s_seq = sm;                        // [48][192]
    float* s_buf = sm + TOK_ROWS * 192;       // [48][384]: A = cols 0:192, Bzone = 192:384
    const float* gs = g_scratch;

    const int tid  = threadIdx.x;
    const int warp = tid >> 5, lane = tid & 31;
    const int b0   = blockIdx.x * ROWS_PER_BLOCK;

    // ---- load inputs: perc -> A, tech -> Bzone
    for (int idx = tid; idx < ROWS_PER_BLOCK * 48; idx += NTHREADS) {
        int r = idx / 48, q4 = idx % 48;
        int row = b0 + r; if (row >= B) row = B - 1;
        float4 pv = reinterpret_cast<const float4*>(perc + row * 192)[q4];
        float4 tv = reinterpret_cast<const float4*>(tech + row * 192)[q4];
        reinterpret_cast<float4*>(s_buf + r * 384)[q4] = pv;
        reinterpret_cast<float4*>(s_buf + r * 384 + 192)[q4] = tv;
    }
    __syncthreads();

    // ---- projections: p -> token rows 2r, t -> 2r+1 (s_seq, row stride 192)
    gemm2<24, 192, 192, false, false>(s_buf,       384, gs + OFF_WPT, 192, bp, s_seq,       384, tid);
    gemm2<24, 192, 192, false, false>(s_buf + 192, 384, gs + OFF_WTT, 192, bt, s_seq + 192, 384, tid);
    __syncthreads();

    // ---- per-head: qkv -> A; attention ctx -> Bzone cols h*64
    for (int h = 0; h < 3; ++h) {
        gemm2<48, 192, 192, false, false>(s_seq, 192, gs + OFF_INWGT + h * 36864, 192,
                                          gs + OFF_INBG + h * 192, s_buf, 384, tid);
        __syncthreads();
        #pragma unroll
        for (int pp = 0; pp < 3; ++pp) {
            int p = warp * 3 + pp;
            float* r0 = s_buf + (2 * p) * 384;
            float* r1 = r0 + 384;
            float q0a = r0[lane],       q0b = r0[lane + 32];
            float k0a = r0[64 + lane],  k0b = r0[96 + lane];
            float v0a = r0[128 + lane], v0b = r0[160 + lane];
            float q1a = r1[lane],       q1b = r1[lane + 32];
            float k1a = r1[64 + lane],  k1b = r1[96 + lane];
            float v1a = r1[128 + lane], v1b = r1[160 + lane];
            float s00 = wredsum(q0a * k0a + q0b * k0b) * 0.125f;
            float s01 = wredsum(q0a * k1a + q0b * k1b) * 0.125f;
            float s10 = wredsum(q1a * k0a + q1b * k0b) * 0.125f;
            float s11 = wredsum(q1a * k1a + q1b * k1b) * 0.125f;
            float m0 = fmaxf(s00, s01);
            float e00 = __expf(s00 - m0), e01 = __expf(s01 - m0);
            float i0 = 1.0f / (e00 + e01);
            float a00 = e00 * i0, a01 = e01 * i0;
            float m1 = fmaxf(s10, s11);
            float e10 = __expf(s10 - m1), e11 = __expf(s11 - m1);
            float i1 = 1.0f / (e10 + e11);
            float a10 = e10 * i1, a11 = e11 * i1;
            int cb = 192 + h * 64;
            r0[cb + lane]      = a00 * v0a + a01 * v1a;
            r0[cb + lane + 32] = a00 * v0b + a01 * v1b;
            r1[cb + lane]      = a10 * v0a + a11 * v1a;
            r1[cb + lane + 32] = a10 * v0b + a11 * v1b;
        }
        __syncthreads();
    }

    // ---- out-proj: ctx (Bzone) -> attn_out (A)
    gemm2<48, 192, 192, false, false>(s_buf + 192, 384, gs + OFF_OUTWT, 192, out_b, s_buf, 384, tid);
    __syncthreads();

    // ---- LN1: x1 = LN(seq + attn_out) -> s_seq
    ln48(s_seq, 192, s_buf, 384, s_seq, ln1_g, ln1_b, tid);
    __syncthreads();

    // ---- FFN, two passes of 192 hidden each
    // pass 1: hidden1 -> A ; partial out (with bias) -> Bzone
    gemm2<48, 192, 192, true,  false>(s_seq, 192, gs + OFF_FFN1T, 384, ffn_b1, s_buf, 384, tid);
    __syncthreads();
    gemm2<48, 192, 192, false, false>(s_buf, 384, gs + OFF_FFN2T, 192, ffn_b2, s_buf + 192, 384, tid);
    __syncthreads();
    // pass 2: hidden2 -> A ; accumulate into Bzone
    gemm2<48, 192, 192, true,  false>(s_seq, 192, gs + OFF_FFN1T + 192, 384, ffn_b1 + 192, s_buf, 384, tid);
    __syncthreads();
    gemm2<48, 192, 192, false, true >(s_buf, 384, gs + OFF_FFN2T + 192 * 192, 192, ffn_b2, s_buf + 192, 384, tid);
    __syncthreads();

    // ---- LN2: x2 = LN(x1 + ffn_out) -> s_seq
    ln48(s_seq, 192, s_buf + 192, 384, s_seq, ln2_g, ln2_b, tid);
    __syncthreads();

    // ---- pool: z[r] -> A rows 0:24
    for (int idx = tid; idx < ROWS_PER_BLOCK * 192; idx += NTHREADS) {
        int r = idx / 192, d = idx % 192;
        s_buf[r * 384 + d] = 0.5f * (s_seq[(2 * r) * 192 + d] + s_seq[(2 * r + 1) * 192 + d]);
    }
    __syncthreads();

    // ---- heads: cls1 (relu) -> Bzone rows 0:24 ; fp -> A rows 24:48
    gemm2<24, 192, 192, true,  false>(s_buf, 384, gs + OFF_CLS1T, 192, cls_b1, s_buf + 192, 384, tid);
    gemm2<24, 128, 192, false, false>(s_buf, 384, gs + OFF_FPT,   128, fp_b,   s_buf + ROWS_PER_BLOCK * 384, 384, tid);
    __syncthreads();

    // ---- cls2 + sigmoid: 24 rows x 3 logits
    if (tid < 72) {
        int r = tid / 3, j = tid % 3;
        const float4* c1 = reinterpret_cast<const float4*>(s_buf + r * 384 + 192);
        const float4* w2 = reinterpret_cast<const float4*>(cls_w2 + j * 192);
        float acc = 0.0f;
        #pragma unroll 8
        for (int q = 0; q < 48; ++q) {
            float4 a = c1[q], w = w2[q];
            acc = fmaf(a.x, w.x, acc); acc = fmaf(a.y, w.y, acc);
            acc = fmaf(a.z, w.z, acc); acc = fmaf(a.w, w.w, acc);
        }
        acc += cls_b2[j];
        float prob = 1.0f / (1.0f + __expf(-acc));
        int row = b0 + r;
        if (row < B) out[j * B + row] = prob;
    }

    // ---- fp normalize + store: warp handles rows 3w..3w+2
    #pragma unroll
    for (int rr = 0; rr < 3; ++rr) {
        int r = warp * 3 + rr;
        const float* fpv = s_buf + (ROWS_PER_BLOCK + r) * 384;
        float f[4];
        float ss = 0.0f;
        #pragma unroll
        for (int i = 0; i < 4; ++i) { f[i] = fpv[lane + 32 * i]; ss = fmaf(f[i], f[i], ss); }
        ss = wredsum(ss);
        float inv = 1.0f / fmaxf(sqrtf(ss), 1e-12f);
        int row = b0 + r;
        if (row < B) {
            float* o = out + 3 * B + row * 128;
            #pragma unroll
            for (int i = 0; i < 4; ++i) o[lane + 32 * i] = f[i] * inv;
        }
    }
}

// ---------------------------------------------------------------------------
// Launch
// ---------------------------------------------------------------------------
extern "C" void kernel_launch(void* const* d_in, const int* in_sizes, int n_in,
                              void* d_out, int out_size) {
    const float* perc   = (const float*)d_in[0];
    const float* tech   = (const float*)d_in[1];
    const float* Wp     = (const float*)d_in[2];
    const float* bp     = (const float*)d_in[3];
    const float* Wt     = (const float*)d_in[4];
    const float* bt     = (const float*)d_in[5];
    const float* in_w   = (const float*)d_in[6];
    const float* in_b   = (const float*)d_in[7];
    const float* out_w  = (const float*)d_in[8];
    const float* out_b  = (const float*)d_in[9];
    const float* ffn_w1 = (const float*)d_in[10];
    const float* ffn_b1 = (const float*)d_in[11];
    const float* ffn_w2 = (const float*)d_in[12];
    const float* ffn_b2 = (const float*)d_in[13];
    const float* ln1_g  = (const float*)d_in[14];
    const float* ln1_b  = (const float*)d_in[15];
    const float* ln2_g  = (const float*)d_in[16];
    const float* ln2_b  = (const float*)d_in[17];
    const float* cls_w1 = (const float*)d_in[18];
    const float* cls_b1 = (const float*)d_in[19];
    const float* cls_w2 = (const float*)d_in[20];
    const float* cls_b2 = (const float*)d_in[21];
    const float* fp_w   = (const float*)d_in[22];
    const float* fp_b   = (const float*)d_in[23];
    float* outp = (float*)d_out;

    const int B = in_sizes[0] / D_MODEL;

    // merged weight prep (runs inside the graph each replay)
    k_prep<<<296, 256>>>(Wp, Wt, out_w, ffn_w1, ffn_w2, cls_w1, fp_w, in_w, in_b);

    const int smemBytes = (TOK_ROWS * 192 + TOK_ROWS * 384) * (int)sizeof(float); // 110592
    cudaFuncSetAttribute(fusion_kernel, cudaFuncAttributeMaxDynamicSharedMemorySize, smemBytes);

    int grid = (B + ROWS_PER_BLOCK - 1) / ROWS_PER_BLOCK;
    fusion_kernel<<<grid, NTHREADS, smemBytes>>>(
        perc, tech, bp, bt, out_b, ffn_b1, ffn_b2,
        ln1_g, ln1_b, ln2_g, ln2_b, cls_b1, cls_w2, cls_b2, fp_b,
        outp, B);
}